// round 11
// baseline (speedup 1.0000x reference)
#include <cuda_runtime.h>
#include <cuda_bf16.h>
#include <math.h>

#define N_NODES 50000
#define N_EDGES 600000
#define D 128
#define REL_DIM 100
#define N_REL 40

// ---------------- device scratch ----------------
__device__ __align__(32) __nv_bfloat16 g_bt[4 * D * D];  // [mat][hi/lo][n][k]
__device__ float g_h[(size_t)N_NODES * D];   // X @ W
__device__ float g_s1[N_NODES];              // h . a[:D]
__device__ float g_s2[N_NODES];              // h . a[D:2D]
__device__ float g_t[N_REL];                 // per-relation logit term
__device__ int   g_cnt[N_NODES];             // edges per dst
__device__ int   g_off[N_NODES];             // CSR segment base per dst
__device__ int   g_cur[N_NODES];             // fill cursor
__device__ int   g_ctr;                      // global bump allocator
__device__ unsigned g_epack[N_EDGES];        // dst-grouped: src | (etype<<16)

// ---------------- K_prep: zero state + split W,Wres to bf16 hi/lo + rel term ----------------
__global__ void k_prep(const float* __restrict__ W, const float* __restrict__ Wres,
                       const float* __restrict__ W_r, const float* __restrict__ a,
                       const float* __restrict__ rel_emb) {
    int i = blockIdx.x * blockDim.x + threadIdx.x;
    if (i == 0) g_ctr = 0;
    if (i < N_NODES) {
        g_cnt[i] = 0;
        g_s1[i] = 0.0f;
        g_s2[i] = 0.0f;
    }
    if (i < 2 * D * D) {
        int mat = i >> 14;              // D*D = 16384
        int rem = i & (D * D - 1);
        int k = rem >> 7, n = rem & 127;
        float w = (mat ? Wres : W)[k * D + n];
        __nv_bfloat16 hi = __float2bfloat16(w);
        __nv_bfloat16 lo = __float2bfloat16(w - __bfloat162float(hi));
        g_bt[((size_t)(mat * 2 + 0) * D + n) * D + k] = hi;
        g_bt[((size_t)(mat * 2 + 1) * D + n) * D + k] = lo;
    }
    if (blockIdx.x == 0) {
        __shared__ float v[REL_DIM];
        int t = threadIdx.x;
        if (t < REL_DIM) {
            float s = 0.0f;
            #pragma unroll 4
            for (int k = 0; k < D; k++) s = fmaf(W_r[t * D + k], a[2 * D + k], s);
            v[t] = s;
        }
        __syncthreads();
        if (t < N_REL) {
            float s = 0.0f;
            for (int j = 0; j < REL_DIM; j++) s = fmaf(rel_emb[t * REL_DIM + j], v[j], s);
            g_t[t] = s;
        }
    }
}

// ---------------- K_hist: edges per dst (4 edges / thread) ----------------
__global__ void k_hist(const int* __restrict__ ei) {
    int i = blockIdx.x * blockDim.x + threadIdx.x;
    if (i >= N_EDGES / 4) return;
    int4 d = *(const int4*)(ei + N_EDGES + 4 * i);
    atomicAdd(&g_cnt[d.x], 1);
    atomicAdd(&g_cnt[d.y], 1);
    atomicAdd(&g_cnt[d.z], 1);
    atomicAdd(&g_cnt[d.w], 1);
}

// ---------------- K_alloc: bump-allocate CSR segments ----------------
__global__ __launch_bounds__(1024) void k_alloc() {
    __shared__ int wsum[32];
    __shared__ int bbase;
    int i = blockIdx.x * 1024 + threadIdx.x;
    int lane = threadIdx.x & 31, wid = threadIdx.x >> 5;
    int c = (i < N_NODES) ? g_cnt[i] : 0;
    int p = c;
    #pragma unroll
    for (int o = 1; o < 32; o <<= 1) {
        int v = __shfl_up_sync(0xFFFFFFFFu, p, o);
        if (lane >= o) p += v;
    }
    if (lane == 31) wsum[wid] = p;
    __syncthreads();
    if (wid == 0) {
        int v = wsum[lane];
        int q = v;
        #pragma unroll
        for (int o = 1; o < 32; o <<= 1) {
            int u = __shfl_up_sync(0xFFFFFFFFu, q, o);
            if (lane >= o) q += u;
        }
        wsum[lane] = q - v;
        if (lane == 31) bbase = atomicAdd(&g_ctr, q);
    }
    __syncthreads();
    if (i < N_NODES) {
        int base = bbase + wsum[wid] + (p - c);
        g_off[i] = base;
        g_cur[i] = base;
    }
}

// ---------------- K_fill: scatter packed (src | et<<16) into CSR (2 edges / thread) ----------------
__global__ void k_fill(const int* __restrict__ ei, const int* __restrict__ et) {
    int i = blockIdx.x * blockDim.x + threadIdx.x;
    if (i >= N_EDGES / 2) return;
    int2 s = *(const int2*)(ei + 2 * i);
    int2 d = *(const int2*)(ei + N_EDGES + 2 * i);
    int2 t = *(const int2*)(et + 2 * i);
    int p0 = atomicAdd(&g_cur[d.x], 1);
    int p1 = atomicAdd(&g_cur[d.y], 1);
    g_epack[p0] = (unsigned)s.x | ((unsigned)t.x << 16);
    g_epack[p1] = (unsigned)s.y | ((unsigned)t.y << 16);
}

// ---------------- ldmatrix helpers ----------------
__device__ __forceinline__ unsigned smem_u32(const void* p) {
    return (unsigned)__cvta_generic_to_shared(p);
}
__device__ __forceinline__ void ldsm_x4(unsigned& r0, unsigned& r1, unsigned& r2,
                                        unsigned& r3, unsigned addr) {
    asm volatile("ldmatrix.sync.aligned.m8n8.x4.shared.b16 {%0,%1,%2,%3}, [%4];"
                 : "=r"(r0), "=r"(r1), "=r"(r2), "=r"(r3) : "r"(addr));
}

// ---------------- K1: tensor-core split-bf16 GEMM (ldmatrix frags) ----------------
#define ASTR 40
__global__ __launch_bounds__(256, 2) void k_gemm_t(const float* __restrict__ X,
                                                   const float* __restrict__ b_res,
                                                   const float* __restrict__ a,
                                                   float* __restrict__ out) {
    __shared__ __align__(16) __nv_bfloat16 AsH[128 * ASTR];
    __shared__ __align__(16) __nv_bfloat16 AsL[128 * ASTR];
    __shared__ __align__(16) __nv_bfloat16 BsH[128 * ASTR];
    __shared__ __align__(16) __nv_bfloat16 BsL[128 * ASTR];
    int tid = threadIdx.x;
    int bm = blockIdx.x * 128;
    int y = blockIdx.y;
    const __nv_bfloat16* BtH = g_bt + (size_t)(y * 2 + 0) * D * D;
    const __nv_bfloat16* BtL = g_bt + (size_t)(y * 2 + 1) * D * D;
    int w = tid >> 5, lane = tid & 31;
    int wm = w & 1, wn = w >> 1;
    int lr = lane >> 2, lc = (lane & 3) * 2;

    float acc[4][4][4];
    #pragma unroll
    for (int i = 0; i < 4; i++)
        #pragma unroll
        for (int j = 0; j < 4; j++)
            #pragma unroll
            for (int q = 0; q < 4; q++) acc[i][j][q] = 0.0f;

    int lm = tid & 127;
    int ls = (tid >> 7) * 16;
    int gm = bm + lm;
    bool valid = gm < N_NODES;

    int arow = lane & 15;
    int acol = (lane >> 4) * 8;
    int nrow = (lane & 7) + ((lane >> 4) & 1) * 8;
    int kcol = ((lane >> 3) & 1) * 8;

    for (int kc = 0; kc < D; kc += 32) {
        float f[16];
        #pragma unroll
        for (int i = 0; i < 4; i++) {
            float4 v = make_float4(0.f, 0.f, 0.f, 0.f);
            if (valid) v = *(const float4*)(X + (size_t)gm * D + kc + ls + i * 4);
            f[i * 4 + 0] = v.x; f[i * 4 + 1] = v.y; f[i * 4 + 2] = v.z; f[i * 4 + 3] = v.w;
        }
        unsigned hp[8], lp[8];
        #pragma unroll
        for (int j = 0; j < 8; j++) {
            __nv_bfloat16 h0 = __float2bfloat16(f[2 * j]);
            __nv_bfloat16 h1 = __float2bfloat16(f[2 * j + 1]);
            __nv_bfloat16 e0 = __float2bfloat16(f[2 * j] - __bfloat162float(h0));
            __nv_bfloat16 e1 = __float2bfloat16(f[2 * j + 1] - __bfloat162float(h1));
            hp[j] = ((unsigned)__bfloat16_as_ushort(h1) << 16) | __bfloat16_as_ushort(h0);
            lp[j] = ((unsigned)__bfloat16_as_ushort(e1) << 16) | __bfloat16_as_ushort(e0);
        }
        __nv_bfloat16* ah = &AsH[lm * ASTR + ls];
        __nv_bfloat16* al = &AsL[lm * ASTR + ls];
        #pragma unroll
        for (int j = 0; j < 4; j++) {
            ((uint2*)ah)[j] = make_uint2(hp[2 * j], hp[2 * j + 1]);
            ((uint2*)al)[j] = make_uint2(lp[2 * j], lp[2 * j + 1]);
        }
        {
            const uint4* qh = (const uint4*)(BtH + (size_t)lm * D + kc + ls);
            const uint4* ql = (const uint4*)(BtL + (size_t)lm * D + kc + ls);
            uint4 h0 = qh[0], h1 = qh[1], l0 = ql[0], l1 = ql[1];
            __nv_bfloat16* bh = &BsH[lm * ASTR + ls];
            __nv_bfloat16* bl = &BsL[lm * ASTR + ls];
            ((uint2*)bh)[0] = make_uint2(h0.x, h0.y);
            ((uint2*)bh)[1] = make_uint2(h0.z, h0.w);
            ((uint2*)bh)[2] = make_uint2(h1.x, h1.y);
            ((uint2*)bh)[3] = make_uint2(h1.z, h1.w);
            ((uint2*)bl)[0] = make_uint2(l0.x, l0.y);
            ((uint2*)bl)[1] = make_uint2(l0.z, l0.w);
            ((uint2*)bl)[2] = make_uint2(l1.x, l1.y);
            ((uint2*)bl)[3] = make_uint2(l1.z, l1.w);
        }
        __syncthreads();

        #pragma unroll
        for (int ks = 0; ks < 32; ks += 16) {
            unsigned afH[4][4], bfH[4][2], bfL[4][2];
            #pragma unroll
            for (int mt = 0; mt < 4; mt++) {
                unsigned ad = smem_u32(&AsH[(wm * 64 + mt * 16 + arow) * ASTR + ks + acol]);
                ldsm_x4(afH[mt][0], afH[mt][1], afH[mt][2], afH[mt][3], ad);
            }
            #pragma unroll
            for (int p = 0; p < 2; p++) {
                unsigned bdh = smem_u32(&BsH[(wn * 32 + p * 16 + nrow) * ASTR + ks + kcol]);
                ldsm_x4(bfH[2 * p][0], bfH[2 * p][1], bfH[2 * p + 1][0], bfH[2 * p + 1][1], bdh);
                unsigned bdl = smem_u32(&BsL[(wn * 32 + p * 16 + nrow) * ASTR + ks + kcol]);
                ldsm_x4(bfL[2 * p][0], bfL[2 * p][1], bfL[2 * p + 1][0], bfL[2 * p + 1][1], bdl);
            }
            #pragma unroll
            for (int mt = 0; mt < 4; mt++)
                #pragma unroll
                for (int nt = 0; nt < 4; nt++) {
                    asm volatile(
                        "mma.sync.aligned.m16n8k16.row.col.f32.bf16.bf16.f32 "
                        "{%0,%1,%2,%3}, {%4,%5,%6,%7}, {%8,%9}, {%0,%1,%2,%3};"
                        : "+f"(acc[mt][nt][0]), "+f"(acc[mt][nt][1]),
                          "+f"(acc[mt][nt][2]), "+f"(acc[mt][nt][3])
                        : "r"(afH[mt][0]), "r"(afH[mt][1]), "r"(afH[mt][2]), "r"(afH[mt][3]),
                          "r"(bfH[nt][0]), "r"(bfH[nt][1]));
                    asm volatile(
                        "mma.sync.aligned.m16n8k16.row.col.f32.bf16.bf16.f32 "
                        "{%0,%1,%2,%3}, {%4,%5,%6,%7}, {%8,%9}, {%0,%1,%2,%3};"
                        : "+f"(acc[mt][nt][0]), "+f"(acc[mt][nt][1]),
                          "+f"(acc[mt][nt][2]), "+f"(acc[mt][nt][3])
                        : "r"(afH[mt][0]), "r"(afH[mt][1]), "r"(afH[mt][2]), "r"(afH[mt][3]),
                          "r"(bfL[nt][0]), "r"(bfL[nt][1]));
                }
            #pragma unroll
            for (int mt = 0; mt < 4; mt++) {
                unsigned a0, a1, a2, a3;
                unsigned ad = smem_u32(&AsL[(wm * 64 + mt * 16 + arow) * ASTR + ks + acol]);
                ldsm_x4(a0, a1, a2, a3, ad);
                #pragma unroll
                for (int nt = 0; nt < 4; nt++)
                    asm volatile(
                        "mma.sync.aligned.m16n8k16.row.col.f32.bf16.bf16.f32 "
                        "{%0,%1,%2,%3}, {%4,%5,%6,%7}, {%8,%9}, {%0,%1,%2,%3};"
                        : "+f"(acc[mt][nt][0]), "+f"(acc[mt][nt][1]),
                          "+f"(acc[mt][nt][2]), "+f"(acc[mt][nt][3])
                        : "r"(a0), "r"(a1), "r"(a2), "r"(a3),
                          "r"(bfH[nt][0]), "r"(bfH[nt][1]));
            }
        }
        __syncthreads();
    }

    if (y == 0) {
        #pragma unroll
        for (int mt = 0; mt < 4; mt++) {
            int r0 = bm + wm * 64 + mt * 16 + lr;
            float p1a = 0.f, p2a = 0.f, p1b = 0.f, p2b = 0.f;
            #pragma unroll
            for (int nt = 0; nt < 4; nt++) {
                int c0 = wn * 32 + nt * 8 + lc;
                float a1x = a[c0], a1y = a[c0 + 1];
                float a2x = a[D + c0], a2y = a[D + c0 + 1];
                if (r0 < N_NODES)
                    *(float2*)&g_h[(size_t)r0 * D + c0] =
                        make_float2(acc[mt][nt][0], acc[mt][nt][1]);
                if (r0 + 8 < N_NODES)
                    *(float2*)&g_h[(size_t)(r0 + 8) * D + c0] =
                        make_float2(acc[mt][nt][2], acc[mt][nt][3]);
                p1a = fmaf(acc[mt][nt][0], a1x, fmaf(acc[mt][nt][1], a1y, p1a));
                p2a = fmaf(acc[mt][nt][0], a2x, fmaf(acc[mt][nt][1], a2y, p2a));
                p1b = fmaf(acc[mt][nt][2], a1x, fmaf(acc[mt][nt][3], a1y, p1b));
                p2b = fmaf(acc[mt][nt][2], a2x, fmaf(acc[mt][nt][3], a2y, p2b));
            }
            #pragma unroll
            for (int o = 1; o <= 2; o <<= 1) {
                p1a += __shfl_xor_sync(0xFFFFFFFFu, p1a, o);
                p2a += __shfl_xor_sync(0xFFFFFFFFu, p2a, o);
                p1b += __shfl_xor_sync(0xFFFFFFFFu, p1b, o);
                p2b += __shfl_xor_sync(0xFFFFFFFFu, p2b, o);
            }
            if ((lane & 3) == 0) {
                if (r0 < N_NODES) {
                    atomicAdd(&g_s1[r0], p1a);
                    atomicAdd(&g_s2[r0], p2a);
                }
                if (r0 + 8 < N_NODES) {
                    atomicAdd(&g_s1[r0 + 8], p1b);
                    atomicAdd(&g_s2[r0 + 8], p2b);
                }
            }
        }
    } else {
        #pragma unroll
        for (int mt = 0; mt < 4; mt++) {
            int r0 = bm + wm * 64 + mt * 16 + lr;
            #pragma unroll
            for (int nt = 0; nt < 4; nt++) {
                int c0 = wn * 32 + nt * 8 + lc;
                float2 br = *(const float2*)(b_res + c0);
                if (r0 < N_NODES)
                    *(float2*)(out + (size_t)r0 * D + c0) =
                        make_float2(acc[mt][nt][0] + br.x, acc[mt][nt][1] + br.y);
                if (r0 + 8 < N_NODES)
                    *(float2*)(out + (size_t)(r0 + 8) * D + c0) =
                        make_float2(acc[mt][nt][2] + br.x, acc[mt][nt][3] + br.y);
            }
        }
    }
}

// ---------------- K_agg: 2 warps per node (64 cols each), softmax duplicated ----------------
__device__ __forceinline__ float edge_logit(unsigned pk, float s1n) {
    float l = s1n + g_s2[pk & 0xFFFFu] + g_t[pk >> 16];
    return l > 0.0f ? l : 0.2f * l;
}

__device__ __forceinline__ float selu_f(float x) {
    const float scale  = 1.0507009873554805f;
    const float salpha = 1.7580993408473766f;
    return x > 0.0f ? scale * x : fmaf(salpha, __expf(x), -salpha);
}

__global__ __launch_bounds__(256) void k_agg(float* __restrict__ out) {
    int wrp  = threadIdx.x >> 5;            // 0..7
    int node = blockIdx.x * 4 + (wrp >> 1); // 4 nodes per block
    int half = wrp & 1;                     // column half
    if (node >= N_NODES) return;
    int lane = threadIdx.x & 31;
    int start = g_off[node];
    int cnt   = g_cnt[node];
    float s1n = g_s1[node];
    int coff  = half * 64 + lane * 2;       // this warp's 2 columns per lane

    float2 acc = make_float2(0.f, 0.f);

    if (cnt > 0) {
        if (cnt <= 32) {
            unsigned pk = 0;
            float l = -INFINITY;
            if (lane < cnt) {
                pk = g_epack[start + lane];
                l = edge_logit(pk, s1n);
            }
            float m = l;
            #pragma unroll
            for (int o = 16; o > 0; o >>= 1)
                m = fmaxf(m, __shfl_xor_sync(0xFFFFFFFFu, m, o));
            float ev = (lane < cnt) ? __expf(l - m) : 0.0f;
            float sum = ev;
            #pragma unroll
            for (int o = 16; o > 0; o >>= 1)
                sum += __shfl_xor_sync(0xFFFFFFFFu, sum, o);
            float al = ev * __fdividef(1.0f, sum + 1e-16f);
            #pragma unroll 8
            for (int j = 0; j < cnt; j++) {
                float aj = __shfl_sync(0xFFFFFFFFu, al, j);
                int   sj = __shfl_sync(0xFFFFFFFFu, (int)pk, j) & 0xFFFF;
                float2 hv = *(const float2*)&g_h[(size_t)sj * D + coff];
                acc.x = fmaf(hv.x, aj, acc.x);
                acc.y = fmaf(hv.y, aj, acc.y);
            }
        } else {
            float m = -INFINITY;
            for (int i = lane; i < cnt; i += 32)
                m = fmaxf(m, edge_logit(g_epack[start + i], s1n));
            #pragma unroll
            for (int o = 16; o > 0; o >>= 1)
                m = fmaxf(m, __shfl_xor_sync(0xFFFFFFFFu, m, o));
            float sum = 0.0f;
            for (int i = lane; i < cnt; i += 32)
                sum += __expf(edge_logit(g_epack[start + i], s1n) - m);
            #pragma unroll
            for (int o = 16; o > 0; o >>= 1)
                sum += __shfl_xor_sync(0xFFFFFFFFu, sum, o);
            float inv = __fdividef(1.0f, sum + 1e-16f);
            for (int i0 = 0; i0 < cnt; i0 += 32) {
                int i = i0 + lane;
                float al = 0.0f;
                unsigned pk = 0;
                if (i < cnt) {
                    pk = g_epack[start + i];
                    al = __expf(edge_logit(pk, s1n) - m) * inv;
                }
                int n = min(32, cnt - i0);
                #pragma unroll 8
                for (int j = 0; j < n; j++) {
                    float aj = __shfl_sync(0xFFFFFFFFu, al, j);
                    int   sj = __shfl_sync(0xFFFFFFFFu, (int)pk, j) & 0xFFFF;
                    float2 hv = *(const float2*)&g_h[(size_t)sj * D + coff];
                    acc.x = fmaf(hv.x, aj, acc.x);
                    acc.y = fmaf(hv.y, aj, acc.y);
                }
            }
        }
    }

    float* o = out + (size_t)node * D + coff;
    float2 r = *(float2*)o;
    r.x = selu_f(r.x + acc.x);
    r.y = selu_f(r.y + acc.y);
    *(float2*)o = r;
}

// ---------------- launch (fork edge-prep onto a side stream, overlap with GEMM) ----------------
extern "C" void kernel_launch(void* const* d_in, const int* in_sizes, int n_in,
                              void* d_out, int out_size) {
    const float* X      = (const float*)d_in[0];
    const int*   ei     = (const int*)  d_in[1];
    const int*   et     = (const int*)  d_in[2];
    const float* W      = (const float*)d_in[3];
    const float* W_r    = (const float*)d_in[4];
    const float* a      = (const float*)d_in[5];
    const float* W_res  = (const float*)d_in[6];
    const float* b_res  = (const float*)d_in[7];
    const float* rel    = (const float*)d_in[8];
    float* out = (float*)d_out;

    static cudaStream_t s2 = nullptr;
    static cudaEvent_t evF = nullptr, evJ = nullptr;
    if (s2 == nullptr) {
        cudaStreamCreateWithFlags(&s2, cudaStreamNonBlocking);
        cudaEventCreateWithFlags(&evF, cudaEventDisableTiming);
        cudaEventCreateWithFlags(&evJ, cudaEventDisableTiming);
    }

    k_prep<<<(N_NODES + 255) / 256, 256>>>(W, W_res, W_r, a, rel);

    cudaEventRecord(evF, 0);
    cudaStreamWaitEvent(s2, evF, 0);
    k_hist<<<(N_EDGES / 4 + 255) / 256, 256, 0, s2>>>(ei);
    k_alloc<<<(N_NODES + 1023) / 1024, 1024, 0, s2>>>();
    k_fill<<<(N_EDGES / 2 + 255) / 256, 256, 0, s2>>>(ei, et);
    cudaEventRecord(evJ, s2);

    dim3 ggrid((N_NODES + 127) / 128, 2);
    k_gemm_t<<<ggrid, 256>>>(X, b_res, a, out);

    cudaStreamWaitEvent(0, evJ, 0);
    k_agg<<<(N_NODES + 3) / 4, 256>>>(out);
}

// round 12
// speedup vs baseline: 1.1684x; 1.1684x over previous
#include <cuda_runtime.h>
#include <cuda_bf16.h>
#include <cuda_fp16.h>
#include <math.h>

#define N_NODES 50000
#define N_EDGES 600000
#define D 128
#define REL_DIM 100
#define N_REL 40

// ---------------- device scratch ----------------
__device__ __align__(32) __nv_bfloat16 g_bt[4 * D * D];  // [mat][hi/lo][n][k]
__device__ __align__(16) unsigned g_hh[(size_t)N_NODES * (D / 2)];  // h in fp16 (half2 packed)
__device__ float g_s1[N_NODES];              // h . a[:D]
__device__ float g_s2[N_NODES];              // h . a[D:2D]
__device__ float g_t[N_REL];                 // per-relation logit term
__device__ int   g_cnt[N_NODES];             // edges per dst
__device__ int   g_off[N_NODES];             // CSR segment base per dst
__device__ int   g_cur[N_NODES];             // fill cursor
__device__ int   g_ctr;                      // global bump allocator
__device__ unsigned g_epack[N_EDGES];        // dst-grouped: src | (etype<<16)

// ---------------- K_prep: zero state + split W,Wres to bf16 hi/lo + rel term ----------------
__global__ void k_prep(const float* __restrict__ W, const float* __restrict__ Wres,
                       const float* __restrict__ W_r, const float* __restrict__ a,
                       const float* __restrict__ rel_emb) {
    int i = blockIdx.x * blockDim.x + threadIdx.x;
    if (i == 0) g_ctr = 0;
    if (i < N_NODES) {
        g_cnt[i] = 0;
        g_s1[i] = 0.0f;
        g_s2[i] = 0.0f;
    }
    if (i < 2 * D * D) {
        int mat = i >> 14;              // D*D = 16384
        int rem = i & (D * D - 1);
        int k = rem >> 7, n = rem & 127;
        float w = (mat ? Wres : W)[k * D + n];
        __nv_bfloat16 hi = __float2bfloat16(w);
        __nv_bfloat16 lo = __float2bfloat16(w - __bfloat162float(hi));
        g_bt[((size_t)(mat * 2 + 0) * D + n) * D + k] = hi;
        g_bt[((size_t)(mat * 2 + 1) * D + n) * D + k] = lo;
    }
    if (blockIdx.x == 0) {
        __shared__ float v[REL_DIM];
        int t = threadIdx.x;
        if (t < REL_DIM) {
            float s = 0.0f;
            #pragma unroll 4
            for (int k = 0; k < D; k++) s = fmaf(W_r[t * D + k], a[2 * D + k], s);
            v[t] = s;
        }
        __syncthreads();
        if (t < N_REL) {
            float s = 0.0f;
            for (int j = 0; j < REL_DIM; j++) s = fmaf(rel_emb[t * REL_DIM + j], v[j], s);
            g_t[t] = s;
        }
    }
}

// ---------------- K_hist: edges per dst (4 edges / thread) ----------------
__global__ void k_hist(const int* __restrict__ ei) {
    int i = blockIdx.x * blockDim.x + threadIdx.x;
    if (i >= N_EDGES / 4) return;
    int4 d = *(const int4*)(ei + N_EDGES + 4 * i);
    atomicAdd(&g_cnt[d.x], 1);
    atomicAdd(&g_cnt[d.y], 1);
    atomicAdd(&g_cnt[d.z], 1);
    atomicAdd(&g_cnt[d.w], 1);
}

// ---------------- K_alloc: bump-allocate CSR segments ----------------
__global__ __launch_bounds__(1024) void k_alloc() {
    __shared__ int wsum[32];
    __shared__ int bbase;
    int i = blockIdx.x * 1024 + threadIdx.x;
    int lane = threadIdx.x & 31, wid = threadIdx.x >> 5;
    int c = (i < N_NODES) ? g_cnt[i] : 0;
    int p = c;
    #pragma unroll
    for (int o = 1; o < 32; o <<= 1) {
        int v = __shfl_up_sync(0xFFFFFFFFu, p, o);
        if (lane >= o) p += v;
    }
    if (lane == 31) wsum[wid] = p;
    __syncthreads();
    if (wid == 0) {
        int v = wsum[lane];
        int q = v;
        #pragma unroll
        for (int o = 1; o < 32; o <<= 1) {
            int u = __shfl_up_sync(0xFFFFFFFFu, q, o);
            if (lane >= o) q += u;
        }
        wsum[lane] = q - v;
        if (lane == 31) bbase = atomicAdd(&g_ctr, q);
    }
    __syncthreads();
    if (i < N_NODES) {
        int base = bbase + wsum[wid] + (p - c);
        g_off[i] = base;
        g_cur[i] = base;
    }
}

// ---------------- K_fill: scatter packed (src | et<<16) into CSR (2 edges / thread) ----------------
__global__ void k_fill(const int* __restrict__ ei, const int* __restrict__ et) {
    int i = blockIdx.x * blockDim.x + threadIdx.x;
    if (i >= N_EDGES / 2) return;
    int2 s = *(const int2*)(ei + 2 * i);
    int2 d = *(const int2*)(ei + N_EDGES + 2 * i);
    int2 t = *(const int2*)(et + 2 * i);
    int p0 = atomicAdd(&g_cur[d.x], 1);
    int p1 = atomicAdd(&g_cur[d.y], 1);
    g_epack[p0] = (unsigned)s.x | ((unsigned)t.x << 16);
    g_epack[p1] = (unsigned)s.y | ((unsigned)t.y << 16);
}

// ---------------- ldmatrix helpers ----------------
__device__ __forceinline__ unsigned smem_u32(const void* p) {
    return (unsigned)__cvta_generic_to_shared(p);
}
__device__ __forceinline__ void ldsm_x4(unsigned& r0, unsigned& r1, unsigned& r2,
                                        unsigned& r3, unsigned addr) {
    asm volatile("ldmatrix.sync.aligned.m8n8.x4.shared.b16 {%0,%1,%2,%3}, [%4];"
                 : "=r"(r0), "=r"(r1), "=r"(r2), "=r"(r3) : "r"(addr));
}

// ---------------- K1: tensor-core split-bf16 GEMM (ldmatrix frags) ----------------
#define ASTR 40
__global__ __launch_bounds__(256, 2) void k_gemm_t(const float* __restrict__ X,
                                                   const float* __restrict__ b_res,
                                                   const float* __restrict__ a,
                                                   float* __restrict__ out) {
    __shared__ __align__(16) __nv_bfloat16 AsH[128 * ASTR];
    __shared__ __align__(16) __nv_bfloat16 AsL[128 * ASTR];
    __shared__ __align__(16) __nv_bfloat16 BsH[128 * ASTR];
    __shared__ __align__(16) __nv_bfloat16 BsL[128 * ASTR];
    int tid = threadIdx.x;
    int bm = blockIdx.x * 128;
    int y = blockIdx.y;
    const __nv_bfloat16* BtH = g_bt + (size_t)(y * 2 + 0) * D * D;
    const __nv_bfloat16* BtL = g_bt + (size_t)(y * 2 + 1) * D * D;
    int w = tid >> 5, lane = tid & 31;
    int wm = w & 1, wn = w >> 1;
    int lr = lane >> 2, lc = (lane & 3) * 2;

    float acc[4][4][4];
    #pragma unroll
    for (int i = 0; i < 4; i++)
        #pragma unroll
        for (int j = 0; j < 4; j++)
            #pragma unroll
            for (int q = 0; q < 4; q++) acc[i][j][q] = 0.0f;

    int lm = tid & 127;
    int ls = (tid >> 7) * 16;
    int gm = bm + lm;
    bool valid = gm < N_NODES;

    int arow = lane & 15;
    int acol = (lane >> 4) * 8;
    int nrow = (lane & 7) + ((lane >> 4) & 1) * 8;
    int kcol = ((lane >> 3) & 1) * 8;

    for (int kc = 0; kc < D; kc += 32) {
        float f[16];
        #pragma unroll
        for (int i = 0; i < 4; i++) {
            float4 v = make_float4(0.f, 0.f, 0.f, 0.f);
            if (valid) v = *(const float4*)(X + (size_t)gm * D + kc + ls + i * 4);
            f[i * 4 + 0] = v.x; f[i * 4 + 1] = v.y; f[i * 4 + 2] = v.z; f[i * 4 + 3] = v.w;
        }
        unsigned hp[8], lp[8];
        #pragma unroll
        for (int j = 0; j < 8; j++) {
            __nv_bfloat16 h0 = __float2bfloat16(f[2 * j]);
            __nv_bfloat16 h1 = __float2bfloat16(f[2 * j + 1]);
            __nv_bfloat16 e0 = __float2bfloat16(f[2 * j] - __bfloat162float(h0));
            __nv_bfloat16 e1 = __float2bfloat16(f[2 * j + 1] - __bfloat162float(h1));
            hp[j] = ((unsigned)__bfloat16_as_ushort(h1) << 16) | __bfloat16_as_ushort(h0);
            lp[j] = ((unsigned)__bfloat16_as_ushort(e1) << 16) | __bfloat16_as_ushort(e0);
        }
        __nv_bfloat16* ah = &AsH[lm * ASTR + ls];
        __nv_bfloat16* al = &AsL[lm * ASTR + ls];
        #pragma unroll
        for (int j = 0; j < 4; j++) {
            ((uint2*)ah)[j] = make_uint2(hp[2 * j], hp[2 * j + 1]);
            ((uint2*)al)[j] = make_uint2(lp[2 * j], lp[2 * j + 1]);
        }
        {
            const uint4* qh = (const uint4*)(BtH + (size_t)lm * D + kc + ls);
            const uint4* ql = (const uint4*)(BtL + (size_t)lm * D + kc + ls);
            uint4 h0 = qh[0], h1 = qh[1], l0 = ql[0], l1 = ql[1];
            __nv_bfloat16* bh = &BsH[lm * ASTR + ls];
            __nv_bfloat16* bl = &BsL[lm * ASTR + ls];
            ((uint2*)bh)[0] = make_uint2(h0.x, h0.y);
            ((uint2*)bh)[1] = make_uint2(h0.z, h0.w);
            ((uint2*)bh)[2] = make_uint2(h1.x, h1.y);
            ((uint2*)bh)[3] = make_uint2(h1.z, h1.w);
            ((uint2*)bl)[0] = make_uint2(l0.x, l0.y);
            ((uint2*)bl)[1] = make_uint2(l0.z, l0.w);
            ((uint2*)bl)[2] = make_uint2(l1.x, l1.y);
            ((uint2*)bl)[3] = make_uint2(l1.z, l1.w);
        }
        __syncthreads();

        #pragma unroll
        for (int ks = 0; ks < 32; ks += 16) {
            unsigned afH[4][4], bfH[4][2], bfL[4][2];
            #pragma unroll
            for (int mt = 0; mt < 4; mt++) {
                unsigned ad = smem_u32(&AsH[(wm * 64 + mt * 16 + arow) * ASTR + ks + acol]);
                ldsm_x4(afH[mt][0], afH[mt][1], afH[mt][2], afH[mt][3], ad);
            }
            #pragma unroll
            for (int p = 0; p < 2; p++) {
                unsigned bdh = smem_u32(&BsH[(wn * 32 + p * 16 + nrow) * ASTR + ks + kcol]);
                ldsm_x4(bfH[2 * p][0], bfH[2 * p][1], bfH[2 * p + 1][0], bfH[2 * p + 1][1], bdh);
                unsigned bdl = smem_u32(&BsL[(wn * 32 + p * 16 + nrow) * ASTR + ks + kcol]);
                ldsm_x4(bfL[2 * p][0], bfL[2 * p][1], bfL[2 * p + 1][0], bfL[2 * p + 1][1], bdl);
            }
            #pragma unroll
            for (int mt = 0; mt < 4; mt++)
                #pragma unroll
                for (int nt = 0; nt < 4; nt++) {
                    asm volatile(
                        "mma.sync.aligned.m16n8k16.row.col.f32.bf16.bf16.f32 "
                        "{%0,%1,%2,%3}, {%4,%5,%6,%7}, {%8,%9}, {%0,%1,%2,%3};"
                        : "+f"(acc[mt][nt][0]), "+f"(acc[mt][nt][1]),
                          "+f"(acc[mt][nt][2]), "+f"(acc[mt][nt][3])
                        : "r"(afH[mt][0]), "r"(afH[mt][1]), "r"(afH[mt][2]), "r"(afH[mt][3]),
                          "r"(bfH[nt][0]), "r"(bfH[nt][1]));
                    asm volatile(
                        "mma.sync.aligned.m16n8k16.row.col.f32.bf16.bf16.f32 "
                        "{%0,%1,%2,%3}, {%4,%5,%6,%7}, {%8,%9}, {%0,%1,%2,%3};"
                        : "+f"(acc[mt][nt][0]), "+f"(acc[mt][nt][1]),
                          "+f"(acc[mt][nt][2]), "+f"(acc[mt][nt][3])
                        : "r"(afH[mt][0]), "r"(afH[mt][1]), "r"(afH[mt][2]), "r"(afH[mt][3]),
                          "r"(bfL[nt][0]), "r"(bfL[nt][1]));
                }
            #pragma unroll
            for (int mt = 0; mt < 4; mt++) {
                unsigned a0, a1, a2, a3;
                unsigned ad = smem_u32(&AsL[(wm * 64 + mt * 16 + arow) * ASTR + ks + acol]);
                ldsm_x4(a0, a1, a2, a3, ad);
                #pragma unroll
                for (int nt = 0; nt < 4; nt++)
                    asm volatile(
                        "mma.sync.aligned.m16n8k16.row.col.f32.bf16.bf16.f32 "
                        "{%0,%1,%2,%3}, {%4,%5,%6,%7}, {%8,%9}, {%0,%1,%2,%3};"
                        : "+f"(acc[mt][nt][0]), "+f"(acc[mt][nt][1]),
                          "+f"(acc[mt][nt][2]), "+f"(acc[mt][nt][3])
                        : "r"(a0), "r"(a1), "r"(a2), "r"(a3),
                          "r"(bfH[nt][0]), "r"(bfH[nt][1]));
            }
        }
        __syncthreads();
    }

    if (y == 0) {
        // write h as packed fp16 + fused s1/s2 dots (from fp32 accumulators)
        #pragma unroll
        for (int mt = 0; mt < 4; mt++) {
            int r0 = bm + wm * 64 + mt * 16 + lr;
            float p1a = 0.f, p2a = 0.f, p1b = 0.f, p2b = 0.f;
            #pragma unroll
            for (int nt = 0; nt < 4; nt++) {
                int c0 = wn * 32 + nt * 8 + lc;
                float a1x = a[c0], a1y = a[c0 + 1];
                float a2x = a[D + c0], a2y = a[D + c0 + 1];
                if (r0 < N_NODES) {
                    __half2 hv = __floats2half2_rn(acc[mt][nt][0], acc[mt][nt][1]);
                    g_hh[(size_t)r0 * (D / 2) + (c0 >> 1)] = *(unsigned*)&hv;
                }
                if (r0 + 8 < N_NODES) {
                    __half2 hv = __floats2half2_rn(acc[mt][nt][2], acc[mt][nt][3]);
                    g_hh[(size_t)(r0 + 8) * (D / 2) + (c0 >> 1)] = *(unsigned*)&hv;
                }
                p1a = fmaf(acc[mt][nt][0], a1x, fmaf(acc[mt][nt][1], a1y, p1a));
                p2a = fmaf(acc[mt][nt][0], a2x, fmaf(acc[mt][nt][1], a2y, p2a));
                p1b = fmaf(acc[mt][nt][2], a1x, fmaf(acc[mt][nt][3], a1y, p1b));
                p2b = fmaf(acc[mt][nt][2], a2x, fmaf(acc[mt][nt][3], a2y, p2b));
            }
            #pragma unroll
            for (int o = 1; o <= 2; o <<= 1) {
                p1a += __shfl_xor_sync(0xFFFFFFFFu, p1a, o);
                p2a += __shfl_xor_sync(0xFFFFFFFFu, p2a, o);
                p1b += __shfl_xor_sync(0xFFFFFFFFu, p1b, o);
                p2b += __shfl_xor_sync(0xFFFFFFFFu, p2b, o);
            }
            if ((lane & 3) == 0) {
                if (r0 < N_NODES) {
                    atomicAdd(&g_s1[r0], p1a);
                    atomicAdd(&g_s2[r0], p2a);
                }
                if (r0 + 8 < N_NODES) {
                    atomicAdd(&g_s1[r0 + 8], p1b);
                    atomicAdd(&g_s2[r0 + 8], p2b);
                }
            }
        }
    } else {
        #pragma unroll
        for (int mt = 0; mt < 4; mt++) {
            int r0 = bm + wm * 64 + mt * 16 + lr;
            #pragma unroll
            for (int nt = 0; nt < 4; nt++) {
                int c0 = wn * 32 + nt * 8 + lc;
                float2 br = *(const float2*)(b_res + c0);
                if (r0 < N_NODES)
                    *(float2*)(out + (size_t)r0 * D + c0) =
                        make_float2(acc[mt][nt][0] + br.x, acc[mt][nt][1] + br.y);
                if (r0 + 8 < N_NODES)
                    *(float2*)(out + (size_t)(r0 + 8) * D + c0) =
                        make_float2(acc[mt][nt][2] + br.x, acc[mt][nt][3] + br.y);
            }
        }
    }
}

// ---------------- K_agg: warp per node, fp16 h gathers ----------------
__device__ __forceinline__ float edge_logit(unsigned pk, float s1n) {
    float l = s1n + g_s2[pk & 0xFFFFu] + g_t[pk >> 16];
    return l > 0.0f ? l : 0.2f * l;
}

__device__ __forceinline__ float selu_f(float x) {
    const float scale  = 1.0507009873554805f;
    const float salpha = 1.7580993408473766f;
    return x > 0.0f ? scale * x : fmaf(salpha, __expf(x), -salpha);
}

__global__ __launch_bounds__(256) void k_agg(float* __restrict__ out) {
    int node = blockIdx.x * 8 + (threadIdx.x >> 5);
    if (node >= N_NODES) return;
    int lane = threadIdx.x & 31;
    int start = g_off[node];
    int cnt   = g_cnt[node];
    float s1n = g_s1[node];

    float4 acc = make_float4(0.f, 0.f, 0.f, 0.f);

    if (cnt > 0) {
        if (cnt <= 32) {
            unsigned pk = 0;
            float l = -INFINITY;
            if (lane < cnt) {
                pk = g_epack[start + lane];
                l = edge_logit(pk, s1n);
            }
            float m = l;
            #pragma unroll
            for (int o = 16; o > 0; o >>= 1)
                m = fmaxf(m, __shfl_xor_sync(0xFFFFFFFFu, m, o));
            float ev = (lane < cnt) ? __expf(l - m) : 0.0f;
            float sum = ev;
            #pragma unroll
            for (int o = 16; o > 0; o >>= 1)
                sum += __shfl_xor_sync(0xFFFFFFFFu, sum, o);
            float al = ev * __fdividef(1.0f, sum + 1e-16f);
            #pragma unroll 4
            for (int j = 0; j < cnt; j++) {
                float aj = __shfl_sync(0xFFFFFFFFu, al, j);
                int   sj = __shfl_sync(0xFFFFFFFFu, (int)pk, j) & 0xFFFF;
                uint2 hw = *(const uint2*)&g_hh[(size_t)sj * (D / 2) + lane * 2];
                float2 f0 = __half22float2(*(__half2*)&hw.x);
                float2 f1 = __half22float2(*(__half2*)&hw.y);
                acc.x = fmaf(f0.x, aj, acc.x);
                acc.y = fmaf(f0.y, aj, acc.y);
                acc.z = fmaf(f1.x, aj, acc.z);
                acc.w = fmaf(f1.y, aj, acc.w);
            }
        } else {
            float m = -INFINITY;
            for (int i = lane; i < cnt; i += 32)
                m = fmaxf(m, edge_logit(g_epack[start + i], s1n));
            #pragma unroll
            for (int o = 16; o > 0; o >>= 1)
                m = fmaxf(m, __shfl_xor_sync(0xFFFFFFFFu, m, o));
            float sum = 0.0f;
            for (int i = lane; i < cnt; i += 32)
                sum += __expf(edge_logit(g_epack[start + i], s1n) - m);
            #pragma unroll
            for (int o = 16; o > 0; o >>= 1)
                sum += __shfl_xor_sync(0xFFFFFFFFu, sum, o);
            float inv = __fdividef(1.0f, sum + 1e-16f);
            for (int i0 = 0; i0 < cnt; i0 += 32) {
                int i = i0 + lane;
                float al = 0.0f;
                unsigned pk = 0;
                if (i < cnt) {
                    pk = g_epack[start + i];
                    al = __expf(edge_logit(pk, s1n) - m) * inv;
                }
                int n = min(32, cnt - i0);
                #pragma unroll 4
                for (int j = 0; j < n; j++) {
                    float aj = __shfl_sync(0xFFFFFFFFu, al, j);
                    int   sj = __shfl_sync(0xFFFFFFFFu, (int)pk, j) & 0xFFFF;
                    uint2 hw = *(const uint2*)&g_hh[(size_t)sj * (D / 2) + lane * 2];
                    float2 f0 = __half22float2(*(__half2*)&hw.x);
                    float2 f1 = __half22float2(*(__half2*)&hw.y);
                    acc.x = fmaf(f0.x, aj, acc.x);
                    acc.y = fmaf(f0.y, aj, acc.y);
                    acc.z = fmaf(f1.x, aj, acc.z);
                    acc.w = fmaf(f1.y, aj, acc.w);
                }
            }
        }
    }

    float* o = out + (size_t)node * D + lane * 4;
    float4 r = *(float4*)o;
    r.x = selu_f(r.x + acc.x);
    r.y = selu_f(r.y + acc.y);
    r.z = selu_f(r.z + acc.z);
    r.w = selu_f(r.w + acc.w);
    *(float4*)o = r;
}

// ---------------- launch (fork edge-prep onto a side stream, overlap with GEMM) ----------------
extern "C" void kernel_launch(void* const* d_in, const int* in_sizes, int n_in,
                              void* d_out, int out_size) {
    const float* X      = (const float*)d_in[0];
    const int*   ei     = (const int*)  d_in[1];
    const int*   et     = (const int*)  d_in[2];
    const float* W      = (const float*)d_in[3];
    const float* W_r    = (const float*)d_in[4];
    const float* a      = (const float*)d_in[5];
    const float* W_res  = (const float*)d_in[6];
    const float* b_res  = (const float*)d_in[7];
    const float* rel    = (const float*)d_in[8];
    float* out = (float*)d_out;

    static cudaStream_t s2 = nullptr;
    static cudaEvent_t evF = nullptr, evJ = nullptr;
    if (s2 == nullptr) {
        cudaStreamCreateWithFlags(&s2, cudaStreamNonBlocking);
        cudaEventCreateWithFlags(&evF, cudaEventDisableTiming);
        cudaEventCreateWithFlags(&evJ, cudaEventDisableTiming);
    }

    k_prep<<<(N_NODES + 255) / 256, 256>>>(W, W_res, W_r, a, rel);

    cudaEventRecord(evF, 0);
    cudaStreamWaitEvent(s2, evF, 0);
    k_hist<<<(N_EDGES / 4 + 255) / 256, 256, 0, s2>>>(ei);
    k_alloc<<<(N_NODES + 1023) / 1024, 1024, 0, s2>>>();
    k_fill<<<(N_EDGES / 2 + 255) / 256, 256, 0, s2>>>(ei, et);
    cudaEventRecord(evJ, s2);

    dim3 ggrid((N_NODES + 127) / 128, 2);
    k_gemm_t<<<ggrid, 256>>>(X, b_res, a, out);

    cudaStreamWaitEvent(0, evJ, 0);
    k_agg<<<(N_NODES + 7) / 8, 256>>>(out);
}

// round 15
// speedup vs baseline: 1.2650x; 1.0827x over previous
#include <cuda_runtime.h>
#include <cuda_bf16.h>
#include <cuda_fp16.h>
#include <math.h>
#include <stdint.h>

#define N_NODES 50000
#define N_EDGES 600000
#define D 128
#define REL_DIM 100
#define N_REL 40

// ---------------- device scratch ----------------
__device__ __align__(32) __nv_bfloat16 g_bt[4 * D * D];  // [mat][hi/lo][n][k]
__device__ __align__(16) unsigned g_hh[(size_t)N_NODES * (D / 2)];  // h in fp16 (half2)
__device__ float g_s1[N_NODES];
__device__ float g_s2[N_NODES];
__device__ float g_t[N_REL];
__device__ int   g_cnt[N_NODES];
__device__ int   g_off[N_NODES];
__device__ int   g_cur[N_NODES];
__device__ int   g_ctr;
__device__ unsigned g_epack[N_EDGES];

// ---------------- K_prep: zero state + split W,Wres to bf16 hi/lo + rel term ----------------
__global__ void k_prep(const float* __restrict__ W, const float* __restrict__ Wres,
                       const float* __restrict__ W_r, const float* __restrict__ a,
                       const float* __restrict__ rel_emb) {
    int i = blockIdx.x * blockDim.x + threadIdx.x;
    if (i == 0) g_ctr = 0;
    if (i < N_NODES) {
        g_cnt[i] = 0;
        g_s1[i] = 0.0f;
        g_s2[i] = 0.0f;
    }
    if (i < 2 * D * D) {
        int mat = i >> 14;
        int rem = i & (D * D - 1);
        int k = rem >> 7, n = rem & 127;
        float w = (mat ? Wres : W)[k * D + n];
        __nv_bfloat16 hi = __float2bfloat16(w);
        __nv_bfloat16 lo = __float2bfloat16(w - __bfloat162float(hi));
        g_bt[((size_t)(mat * 2 + 0) * D + n) * D + k] = hi;
        g_bt[((size_t)(mat * 2 + 1) * D + n) * D + k] = lo;
    }
    if (blockIdx.x == 0) {
        __shared__ float v[REL_DIM];
        int t = threadIdx.x;
        if (t < REL_DIM) {
            float s = 0.0f;
            #pragma unroll 4
            for (int k = 0; k < D; k++) s = fmaf(W_r[t * D + k], a[2 * D + k], s);
            v[t] = s;
        }
        __syncthreads();
        if (t < N_REL) {
            float s = 0.0f;
            for (int j = 0; j < REL_DIM; j++) s = fmaf(rel_emb[t * REL_DIM + j], v[j], s);
            g_t[t] = s;
        }
    }
}

// ---------------- K_hist ----------------
__global__ void k_hist(const int* __restrict__ ei) {
    int i = blockIdx.x * blockDim.x + threadIdx.x;
    if (i >= N_EDGES / 4) return;
    int4 d = *(const int4*)(ei + N_EDGES + 4 * i);
    atomicAdd(&g_cnt[d.x], 1);
    atomicAdd(&g_cnt[d.y], 1);
    atomicAdd(&g_cnt[d.z], 1);
    atomicAdd(&g_cnt[d.w], 1);
}

// ---------------- K_alloc ----------------
__global__ __launch_bounds__(1024) void k_alloc() {
    __shared__ int wsum[32];
    __shared__ int bbase;
    int i = blockIdx.x * 1024 + threadIdx.x;
    int lane = threadIdx.x & 31, wid = threadIdx.x >> 5;
    int c = (i < N_NODES) ? g_cnt[i] : 0;
    int p = c;
    #pragma unroll
    for (int o = 1; o < 32; o <<= 1) {
        int v = __shfl_up_sync(0xFFFFFFFFu, p, o);
        if (lane >= o) p += v;
    }
    if (lane == 31) wsum[wid] = p;
    __syncthreads();
    if (wid == 0) {
        int v = wsum[lane];
        int q = v;
        #pragma unroll
        for (int o = 1; o < 32; o <<= 1) {
            int u = __shfl_up_sync(0xFFFFFFFFu, q, o);
            if (lane >= o) q += u;
        }
        wsum[lane] = q - v;
        if (lane == 31) bbase = atomicAdd(&g_ctr, q);
    }
    __syncthreads();
    if (i < N_NODES) {
        int base = bbase + wsum[wid] + (p - c);
        g_off[i] = base;
        g_cur[i] = base;
    }
}

// ---------------- K_fill ----------------
__global__ void k_fill(const int* __restrict__ ei, const int* __restrict__ et) {
    int i = blockIdx.x * blockDim.x + threadIdx.x;
    if (i >= N_EDGES / 2) return;
    int2 s = *(const int2*)(ei + 2 * i);
    int2 d = *(const int2*)(ei + N_EDGES + 2 * i);
    int2 t = *(const int2*)(et + 2 * i);
    int p0 = atomicAdd(&g_cur[d.x], 1);
    int p1 = atomicAdd(&g_cur[d.y], 1);
    g_epack[p0] = (unsigned)s.x | ((unsigned)t.x << 16);
    g_epack[p1] = (unsigned)s.y | ((unsigned)t.y << 16);
}

// ---------------- ldmatrix helpers ----------------
__device__ __forceinline__ unsigned smem_u32(const void* p) {
    return (unsigned)__cvta_generic_to_shared(p);
}
__device__ __forceinline__ void ldsm_x4(unsigned& r0, unsigned& r1, unsigned& r2,
                                        unsigned& r3, unsigned addr) {
    asm volatile("ldmatrix.sync.aligned.m8n8.x4.shared.b16 {%0,%1,%2,%3}, [%4];"
                 : "=r"(r0), "=r"(r1), "=r"(r2), "=r"(r3) : "r"(addr));
}

// ---------------- K1: merged tensor-core GEMM — A resident, two B passes ----------------
#define ASTR2 136                       // row stride in bf16 elems (conflict-free ldsm)
#define TILE_E (128 * ASTR2)            // elems per tile
#define GM_SMEM (4 * TILE_E * 2)        // 4 tiles of bf16 bytes = 139264

__global__ __launch_bounds__(256, 1) void k_gemm_m(const float* __restrict__ X,
                                                   const float* __restrict__ b_res,
                                                   const float* __restrict__ a,
                                                   float* __restrict__ out) {
    extern __shared__ __align__(16) __nv_bfloat16 gsm[];
    __nv_bfloat16* AsH = gsm;
    __nv_bfloat16* AsL = AsH + TILE_E;
    __nv_bfloat16* BsH = AsL + TILE_E;
    __nv_bfloat16* BsL = BsH + TILE_E;

    int tid = threadIdx.x;
    int w = tid >> 5, lane = tid & 31;
    int wm = w & 1, wn = w >> 1;
    int lr = lane >> 2, lc = (lane & 3) * 2;
    int bm = blockIdx.x * 128;

    // ---- A: load full 128xK fp32, split hi/lo, store once ----
    {
        int r = tid >> 1, half = tid & 1;
        int gm = bm + r;
        bool valid = gm < N_NODES;
        #pragma unroll
        for (int j = 0; j < 8; j++) {
            int c = half * 64 + j * 8;
            float4 v0 = make_float4(0.f, 0.f, 0.f, 0.f), v1 = v0;
            if (valid) {
                v0 = *(const float4*)(X + (size_t)gm * D + c);
                v1 = *(const float4*)(X + (size_t)gm * D + c + 4);
            }
            float f[8] = {v0.x, v0.y, v0.z, v0.w, v1.x, v1.y, v1.z, v1.w};
            unsigned hp[4], lp[4];
            #pragma unroll
            for (int q = 0; q < 4; q++) {
                __nv_bfloat16 h0 = __float2bfloat16(f[2 * q]);
                __nv_bfloat16 h1 = __float2bfloat16(f[2 * q + 1]);
                __nv_bfloat16 e0 = __float2bfloat16(f[2 * q] - __bfloat162float(h0));
                __nv_bfloat16 e1 = __float2bfloat16(f[2 * q + 1] - __bfloat162float(h1));
                hp[q] = ((unsigned)__bfloat16_as_ushort(h1) << 16) | __bfloat16_as_ushort(h0);
                lp[q] = ((unsigned)__bfloat16_as_ushort(e1) << 16) | __bfloat16_as_ushort(e0);
            }
            *(uint4*)&AsH[r * ASTR2 + c] = make_uint4(hp[0], hp[1], hp[2], hp[3]);
            *(uint4*)&AsL[r * ASTR2 + c] = make_uint4(lp[0], lp[1], lp[2], lp[3]);
        }
    }

    // ldmatrix lane address components
    int arow = lane & 15;
    int acol = (lane >> 4) * 8;
    int nrow = (lane & 7) + ((lane >> 4) & 1) * 8;
    int kcol = ((lane >> 3) & 1) * 8;

    for (int y = 0; y < 2; y++) {
        __syncthreads();   // A stores done (y=0) / previous pass's MMA done (y=1)
        // ---- B: load full 128x128 hi/lo tiles ----
        {
            const __nv_bfloat16* BtH = g_bt + (size_t)(y * 2 + 0) * D * D;
            const __nv_bfloat16* BtL = g_bt + (size_t)(y * 2 + 1) * D * D;
            // 128 rows x 16 chunks(8 elems) = 2048 vec-ops per tile
            for (int idx = tid; idx < 2048; idx += 256) {
                int r = idx >> 4, c = (idx & 15) * 8;
                *(uint4*)&BsH[r * ASTR2 + c] = *(const uint4*)(BtH + (size_t)r * D + c);
                *(uint4*)&BsL[r * ASTR2 + c] = *(const uint4*)(BtL + (size_t)r * D + c);
            }
        }
        __syncthreads();

        float acc[4][4][4];
        #pragma unroll
        for (int i = 0; i < 4; i++)
            #pragma unroll
            for (int j = 0; j < 4; j++)
                #pragma unroll
                for (int q = 0; q < 4; q++) acc[i][j][q] = 0.0f;

        #pragma unroll 2
        for (int ks = 0; ks < 8; ks++) {
            int kofs = ks * 16;
            unsigned afH[4][4], bfH[4][2], bfL[4][2];
            #pragma unroll
            for (int mt = 0; mt < 4; mt++) {
                unsigned ad = smem_u32(&AsH[(wm * 64 + mt * 16 + arow) * ASTR2 + kofs + acol]);
                ldsm_x4(afH[mt][0], afH[mt][1], afH[mt][2], afH[mt][3], ad);
            }
            #pragma unroll
            for (int p = 0; p < 2; p++) {
                unsigned bdh = smem_u32(&BsH[(wn * 32 + p * 16 + nrow) * ASTR2 + kofs + kcol]);
                ldsm_x4(bfH[2 * p][0], bfH[2 * p][1], bfH[2 * p + 1][0], bfH[2 * p + 1][1], bdh);
                unsigned bdl = smem_u32(&BsL[(wn * 32 + p * 16 + nrow) * ASTR2 + kofs + kcol]);
                ldsm_x4(bfL[2 * p][0], bfL[2 * p][1], bfL[2 * p + 1][0], bfL[2 * p + 1][1], bdl);
            }
            #pragma unroll
            for (int mt = 0; mt < 4; mt++)
                #pragma unroll
                for (int nt = 0; nt < 4; nt++) {
                    asm volatile(
                        "mma.sync.aligned.m16n8k16.row.col.f32.bf16.bf16.f32 "
                        "{%0,%1,%2,%3}, {%4,%5,%6,%7}, {%8,%9}, {%0,%1,%2,%3};"
                        : "+f"(acc[mt][nt][0]), "+f"(acc[mt][nt][1]),
                          "+f"(acc[mt][nt][2]), "+f"(acc[mt][nt][3])
                        : "r"(afH[mt][0]), "r"(afH[mt][1]), "r"(afH[mt][2]), "r"(afH[mt][3]),
                          "r"(bfH[nt][0]), "r"(bfH[nt][1]));
                    asm volatile(
                        "mma.sync.aligned.m16n8k16.row.col.f32.bf16.bf16.f32 "
                        "{%0,%1,%2,%3}, {%4,%5,%6,%7}, {%8,%9}, {%0,%1,%2,%3};"
                        : "+f"(acc[mt][nt][0]), "+f"(acc[mt][nt][1]),
                          "+f"(acc[mt][nt][2]), "+f"(acc[mt][nt][3])
                        : "r"(afH[mt][0]), "r"(afH[mt][1]), "r"(afH[mt][2]), "r"(afH[mt][3]),
                          "r"(bfL[nt][0]), "r"(bfL[nt][1]));
                }
            #pragma unroll
            for (int mt = 0; mt < 4; mt++) {
                unsigned a0, a1, a2, a3;
                unsigned ad = smem_u32(&AsL[(wm * 64 + mt * 16 + arow) * ASTR2 + kofs + acol]);
                ldsm_x4(a0, a1, a2, a3, ad);
                #pragma unroll
                for (int nt = 0; nt < 4; nt++)
                    asm volatile(
                        "mma.sync.aligned.m16n8k16.row.col.f32.bf16.bf16.f32 "
                        "{%0,%1,%2,%3}, {%4,%5,%6,%7}, {%8,%9}, {%0,%1,%2,%3};"
                        : "+f"(acc[mt][nt][0]), "+f"(acc[mt][nt][1]),
                          "+f"(acc[mt][nt][2]), "+f"(acc[mt][nt][3])
                        : "r"(a0), "r"(a1), "r"(a2), "r"(a3),
                          "r"(bfH[nt][0]), "r"(bfH[nt][1]));
            }
        }

        // ---- epilogue ----
        if (y == 0) {
            #pragma unroll
            for (int mt = 0; mt < 4; mt++) {
                int r0 = bm + wm * 64 + mt * 16 + lr;
                float p1a = 0.f, p2a = 0.f, p1b = 0.f, p2b = 0.f;
                #pragma unroll
                for (int nt = 0; nt < 4; nt++) {
                    int c0 = wn * 32 + nt * 8 + lc;
                    float a1x = a[c0], a1y = a[c0 + 1];
                    float a2x = a[D + c0], a2y = a[D + c0 + 1];
                    if (r0 < N_NODES) {
                        __half2 hv = __floats2half2_rn(acc[mt][nt][0], acc[mt][nt][1]);
                        g_hh[(size_t)r0 * (D / 2) + (c0 >> 1)] = *(unsigned*)&hv;
                    }
                    if (r0 + 8 < N_NODES) {
                        __half2 hv = __floats2half2_rn(acc[mt][nt][2], acc[mt][nt][3]);
                        g_hh[(size_t)(r0 + 8) * (D / 2) + (c0 >> 1)] = *(unsigned*)&hv;
                    }
                    p1a = fmaf(acc[mt][nt][0], a1x, fmaf(acc[mt][nt][1], a1y, p1a));
                    p2a = fmaf(acc[mt][nt][0], a2x, fmaf(acc[mt][nt][1], a2y, p2a));
                    p1b = fmaf(acc[mt][nt][2], a1x, fmaf(acc[mt][nt][3], a1y, p1b));
                    p2b = fmaf(acc[mt][nt][2], a2x, fmaf(acc[mt][nt][3], a2y, p2b));
                }
                #pragma unroll
                for (int o = 1; o <= 2; o <<= 1) {
                    p1a += __shfl_xor_sync(0xFFFFFFFFu, p1a, o);
                    p2a += __shfl_xor_sync(0xFFFFFFFFu, p2a, o);
                    p1b += __shfl_xor_sync(0xFFFFFFFFu, p1b, o);
                    p2b += __shfl_xor_sync(0xFFFFFFFFu, p2b, o);
                }
                if ((lane & 3) == 0) {
                    if (r0 < N_NODES) {
                        atomicAdd(&g_s1[r0], p1a);
                        atomicAdd(&g_s2[r0], p2a);
                    }
                    if (r0 + 8 < N_NODES) {
                        atomicAdd(&g_s1[r0 + 8], p1b);
                        atomicAdd(&g_s2[r0 + 8], p2b);
                    }
                }
            }
        } else {
            #pragma unroll
            for (int mt = 0; mt < 4; mt++) {
                int r0 = bm + wm * 64 + mt * 16 + lr;
                #pragma unroll
                for (int nt = 0; nt < 4; nt++) {
                    int c0 = wn * 32 + nt * 8 + lc;
                    float2 br = *(const float2*)(b_res + c0);
                    if (r0 < N_NODES)
                        *(float2*)(out + (size_t)r0 * D + c0) =
                            make_float2(acc[mt][nt][0] + br.x, acc[mt][nt][1] + br.y);
                    if (r0 + 8 < N_NODES)
                        *(float2*)(out + (size_t)(r0 + 8) * D + c0) =
                            make_float2(acc[mt][nt][2] + br.x, acc[mt][nt][3] + br.y);
                }
            }
        }
    }
}

// ---------------- K_agg: warp per node, fp16 h gathers ----------------
__device__ __forceinline__ float edge_logit(unsigned pk, float s1n) {
    float l = s1n + g_s2[pk & 0xFFFFu] + g_t[pk >> 16];
    return l > 0.0f ? l : 0.2f * l;
}
__device__ __forceinline__ float selu_f(float x) {
    const float scale  = 1.0507009873554805f;
    const float salpha = 1.7580993408473766f;
    return x > 0.0f ? scale * x : fmaf(salpha, __expf(x), -salpha);
}

__global__ __launch_bounds__(256) void k_agg(float* __restrict__ out) {
    int node = blockIdx.x * 8 + (threadIdx.x >> 5);
    if (node >= N_NODES) return;
    int lane = threadIdx.x & 31;
    int start = g_off[node];
    int cnt   = g_cnt[node];
    float s1n = g_s1[node];

    float4 acc = make_float4(0.f, 0.f, 0.f, 0.f);

    if (cnt > 0) {
        if (cnt <= 32) {
            unsigned pk = 0;
            float l = -INFINITY;
            if (lane < cnt) {
                pk = g_epack[start + lane];
                l = edge_logit(pk, s1n);
            }
            float m = l;
            #pragma unroll
            for (int o = 16; o > 0; o >>= 1)
                m = fmaxf(m, __shfl_xor_sync(0xFFFFFFFFu, m, o));
            float ev = (lane < cnt) ? __expf(l - m) : 0.0f;
            float sum = ev;
            #pragma unroll
            for (int o = 16; o > 0; o >>= 1)
                sum += __shfl_xor_sync(0xFFFFFFFFu, sum, o);
            float al = ev * __fdividef(1.0f, sum + 1e-16f);
            #pragma unroll 4
            for (int j = 0; j < cnt; j++) {
                float aj = __shfl_sync(0xFFFFFFFFu, al, j);
                int   sj = __shfl_sync(0xFFFFFFFFu, (int)pk, j) & 0xFFFF;
                uint2 hw = *(const uint2*)&g_hh[(size_t)sj * (D / 2) + lane * 2];
                float2 f0 = __half22float2(*(__half2*)&hw.x);
                float2 f1 = __half22float2(*(__half2*)&hw.y);
                acc.x = fmaf(f0.x, aj, acc.x);
                acc.y = fmaf(f0.y, aj, acc.y);
                acc.z = fmaf(f1.x, aj, acc.z);
                acc.w = fmaf(f1.y, aj, acc.w);
            }
        } else {
            float m = -INFINITY;
            for (int i = lane; i < cnt; i += 32)
                m = fmaxf(m, edge_logit(g_epack[start + i], s1n));
            #pragma unroll
            for (int o = 16; o > 0; o >>= 1)
                m = fmaxf(m, __shfl_xor_sync(0xFFFFFFFFu, m, o));
            float sum = 0.0f;
            for (int i = lane; i < cnt; i += 32)
                sum += __expf(edge_logit(g_epack[start + i], s1n) - m);
            #pragma unroll
            for (int o = 16; o > 0; o >>= 1)
                sum += __shfl_xor_sync(0xFFFFFFFFu, sum, o);
            float inv = __fdividef(1.0f, sum + 1e-16f);
            for (int i0 = 0; i0 < cnt; i0 += 32) {
                int i = i0 + lane;
                float al = 0.0f;
                unsigned pk = 0;
                if (i < cnt) {
                    pk = g_epack[start + i];
                    al = __expf(edge_logit(pk, s1n) - m) * inv;
                }
                int n = min(32, cnt - i0);
                #pragma unroll 4
                for (int j = 0; j < n; j++) {
                    float aj = __shfl_sync(0xFFFFFFFFu, al, j);
                    int   sj = __shfl_sync(0xFFFFFFFFu, (int)pk, j) & 0xFFFF;
                    uint2 hw = *(const uint2*)&g_hh[(size_t)sj * (D / 2) + lane * 2];
                    float2 f0 = __half22float2(*(__half2*)&hw.x);
                    float2 f1 = __half22float2(*(__half2*)&hw.y);
                    acc.x = fmaf(f0.x, aj, acc.x);
                    acc.y = fmaf(f0.y, aj, acc.y);
                    acc.z = fmaf(f1.x, aj, acc.z);
                    acc.w = fmaf(f1.y, aj, acc.w);
                }
            }
        }
    }

    float* o = out + (size_t)node * D + lane * 4;
    float4 r = *(float4*)o;
    r.x = selu_f(r.x + acc.x);
    r.y = selu_f(r.y + acc.y);
    r.z = selu_f(r.z + acc.z);
    r.w = selu_f(r.w + acc.w);
    *(float4*)o = r;
}

// ---------------- launch ----------------
extern "C" void kernel_launch(void* const* d_in, const int* in_sizes, int n_in,
                              void* d_out, int out_size) {
    const float* X      = (const float*)d_in[0];
    const int*   ei     = (const int*)  d_in[1];
    const int*   et     = (const int*)  d_in[2];
    const float* W      = (const float*)d_in[3];
    const float* W_r    = (const float*)d_in[4];
    const float* a      = (const float*)d_in[5];
    const float* W_res  = (const float*)d_in[6];
    const float* b_res  = (const float*)d_in[7];
    const float* rel    = (const float*)d_in[8];
    float* out = (float*)d_out;

    static cudaStream_t s2 = nullptr;
    static cudaEvent_t evF = nullptr, evJ = nullptr;
    if (s2 == nullptr) {
        cudaStreamCreateWithFlags(&s2, cudaStreamNonBlocking);
        cudaEventCreateWithFlags(&evF, cudaEventDisableTiming);
        cudaEventCreateWithFlags(&evJ, cudaEventDisableTiming);
        cudaFuncSetAttribute(k_gemm_m, cudaFuncAttributeMaxDynamicSharedMemorySize, GM_SMEM);
    }

    k_prep<<<(N_NODES + 255) / 256, 256>>>(W, W_res, W_r, a, rel);

    cudaEventRecord(evF, 0);
    cudaStreamWaitEvent(s2, evF, 0);
    k_hist<<<(N_EDGES / 4 + 255) / 256, 256, 0, s2>>>(ei);
    k_alloc<<<(N_NODES + 1023) / 1024, 1024, 0, s2>>>();
    k_fill<<<(N_EDGES / 2 + 255) / 256, 256, 0, s2>>>(ei, et);
    cudaEventRecord(evJ, s2);

    k_gemm_m<<<(N_NODES + 127) / 128, 256, GM_SMEM>>>(X, b_res, a, out);

    cudaStreamWaitEvent(0, evJ, 0);
    k_agg<<<(N_NODES + 7) / 8, 256>>>(out);
}